// round 2
// baseline (speedup 1.0000x reference)
#include <cuda_runtime.h>

#define B_   8
#define TE_  512
#define TD_  128
#define H_   256
#define DT_  8                 // decoder rows per block
#define ET_  32                // encoder rows per smem tile
#define NTILE (TE_ / ET_)      // 16

// Scratch (allocation-free rule: device globals)
__device__ float g_ep[B_ * TE_ * H_];   // enc @ W_a   [B,TE,H]
__device__ float g_dp[B_ * TD_ * H_];   // dec @ U_a   [B,TD,H]

__device__ __forceinline__ float tanh_fast(float x) {
    float y;
    asm("tanh.approx.f32 %0, %1;" : "=f"(y) : "f"(x));
    return y;
}

// ---------------------------------------------------------------------------
// Fused projection GEMM. z=0: enc[4096,256] @ W_a ; z=1: dec[1024,256] @ U_a
// BM=128, BN=64, BK=16, 256 threads, 8x4 register tile per thread.
// ---------------------------------------------------------------------------
__global__ __launch_bounds__(256) void proj_kernel(
    const float* __restrict__ enc, const float* __restrict__ dec,
    const float* __restrict__ Wa,  const float* __restrict__ Ua)
{
    const int z = blockIdx.z;
    if (z == 1 && blockIdx.x >= (B_ * TD_) / 128) return;

    const float* __restrict__ A = z ? dec : enc;
    const float* __restrict__ W = z ? Ua  : Wa;
    float* __restrict__ P       = z ? g_dp : g_ep;

    __shared__ float As[16][132];   // A^T tile: As[k][m]
    __shared__ float Ws[16][68];    // Ws[k][n]

    const int bm = blockIdx.x * 128;
    const int bn = blockIdx.y * 64;
    const int t  = threadIdx.x;
    const int tx = t & 15;          // n quad (0..15)
    const int ty = t >> 4;          // m octet (0..15)

    float acc[8][4];
#pragma unroll
    for (int i = 0; i < 8; i++)
#pragma unroll
        for (int j = 0; j < 4; j++) acc[i][j] = 0.f;

    const int rowA = t >> 2;        // 0..63
    const int kqA  = t & 3;         // 0..3
    const int kkW  = t >> 4;        // 0..15
    const int nqW  = t & 15;        // 0..15

    for (int k0 = 0; k0 < H_; k0 += 16) {
        // Stage A tile (128 rows x 16 k), transposed into As[k][m]
        {
            float4 a0 = *(const float4*)&A[(bm + rowA) * H_ + k0 + kqA * 4];
            As[kqA * 4 + 0][rowA] = a0.x;
            As[kqA * 4 + 1][rowA] = a0.y;
            As[kqA * 4 + 2][rowA] = a0.z;
            As[kqA * 4 + 3][rowA] = a0.w;
            float4 a1 = *(const float4*)&A[(bm + rowA + 64) * H_ + k0 + kqA * 4];
            As[kqA * 4 + 0][rowA + 64] = a1.x;
            As[kqA * 4 + 1][rowA + 64] = a1.y;
            As[kqA * 4 + 2][rowA + 64] = a1.z;
            As[kqA * 4 + 3][rowA + 64] = a1.w;
            // Stage W tile (16 k x 64 n)
            *(float4*)&Ws[kkW][nqW * 4] =
                *(const float4*)&W[(k0 + kkW) * H_ + bn + nqW * 4];
        }
        __syncthreads();

#pragma unroll
        for (int k = 0; k < 16; k++) {
            float4 a0 = *(float4*)&As[k][ty * 8];
            float4 a1 = *(float4*)&As[k][ty * 8 + 4];
            float4 b  = *(float4*)&Ws[k][tx * 4];
            float av[8] = {a0.x, a0.y, a0.z, a0.w, a1.x, a1.y, a1.z, a1.w};
            float bv[4] = {b.x, b.y, b.z, b.w};
#pragma unroll
            for (int i = 0; i < 8; i++)
#pragma unroll
                for (int j = 0; j < 4; j++) acc[i][j] += av[i] * bv[j];
        }
        __syncthreads();
    }

#pragma unroll
    for (int i = 0; i < 8; i++) {
        float4 o = {acc[i][0], acc[i][1], acc[i][2], acc[i][3]};
        *(float4*)&P[(bm + ty * 8 + i) * H_ + bn + tx * 4] = o;
    }
}

// ---------------------------------------------------------------------------
// Fused score + softmax + context.
// Grid: B * (TD/DT) = 128 blocks, 256 threads (8 warps).
// Warp w owns decoder row d0+w. Lane l owns h-channels [8l, 8l+8):
//   dec_proj and V_a live in registers (loaded once per block).
// ---------------------------------------------------------------------------
__global__ __launch_bounds__(256) void attn_kernel(
    const float* __restrict__ enc, const float* __restrict__ V,
    float* __restrict__ out)
{
    __shared__ float sE[ET_][H_];     // 32 KB: enc_proj / enc tile
    __shared__ float sS[DT_][TE_];    // 16 KB: scores -> weights

    const int t    = threadIdx.x;
    const int lane = t & 31;
    const int w    = t >> 5;                  // 0..7
    const int b    = blockIdx.x >> 4;         // 0..7
    const int d0   = (blockIdx.x & 15) * DT_; // 0..120

    // Per-lane register copies of dec_proj[b, d0+w, 8l..8l+8) and V[8l..8l+8)
    const float* dp = g_dp + (b * TD_ + d0 + w) * H_ + lane * 8;
    const float4 dva = *(const float4*)(dp);
    const float4 dvb = *(const float4*)(dp + 4);
    const float4 va  = *(const float4*)(V + lane * 8);
    const float4 vb  = *(const float4*)(V + lane * 8 + 4);

    const float* ep_base  = g_ep + b * TE_ * H_;
    const float* enc_base = enc  + b * TE_ * H_;

    // ---------------- score phase ----------------
    for (int tile = 0; tile < NTILE; ++tile) {
        const float4* src = (const float4*)(ep_base + tile * ET_ * H_);
        float4* dst = (float4*)&sE[0][0];
#pragma unroll
        for (int i = 0; i < (ET_ * H_ / 4) / 256; ++i)
            dst[t + i * 256] = src[t + i * 256];
        __syncthreads();

        for (int el = 0; el < ET_; ++el) {
            float4 ea = *(float4*)&sE[el][lane * 8];
            float4 eb = *(float4*)&sE[el][lane * 8 + 4];
            float s;
            s  = va.x * tanh_fast(ea.x + dva.x);
            s += va.y * tanh_fast(ea.y + dva.y);
            s += va.z * tanh_fast(ea.z + dva.z);
            s += va.w * tanh_fast(ea.w + dva.w);
            s += vb.x * tanh_fast(eb.x + dvb.x);
            s += vb.y * tanh_fast(eb.y + dvb.y);
            s += vb.z * tanh_fast(eb.z + dvb.z);
            s += vb.w * tanh_fast(eb.w + dvb.w);
#pragma unroll
            for (int o = 16; o > 0; o >>= 1)
                s += __shfl_xor_sync(0xffffffffu, s, o);
            if (lane == 0) sS[w][tile * ET_ + el] = s;
        }
        __syncthreads();
    }

    // ---------------- softmax (warp w handles row w) ----------------
    {
        float vals[16];
        float m = -1e30f;
#pragma unroll
        for (int i = 0; i < 16; i++) {
            vals[i] = sS[w][lane + i * 32];
            m = fmaxf(m, vals[i]);
        }
#pragma unroll
        for (int o = 16; o > 0; o >>= 1)
            m = fmaxf(m, __shfl_xor_sync(0xffffffffu, m, o));
        float sum = 0.f;
#pragma unroll
        for (int i = 0; i < 16; i++) {
            vals[i] = __expf(vals[i] - m);
            sum += vals[i];
        }
#pragma unroll
        for (int o = 16; o > 0; o >>= 1)
            sum += __shfl_xor_sync(0xffffffffu, sum, o);
        const float inv = __fdividef(1.f, sum);
        float* wout = out + B_ * TD_ * H_ + (b * TD_ + d0 + w) * TE_;
#pragma unroll
        for (int i = 0; i < 16; i++) {
            float ww = vals[i] * inv;
            sS[w][lane + i * 32] = ww;
            wout[lane + i * 32]  = ww;
        }
    }
    __syncthreads();

    // ---------------- context phase ----------------
    // Warps 0..3 compute; warp w handles d = w and d = w+4 (halves SMEM reads).
    float acc0[8] = {0, 0, 0, 0, 0, 0, 0, 0};
    float acc1[8] = {0, 0, 0, 0, 0, 0, 0, 0};

    for (int tile = 0; tile < NTILE; ++tile) {
        const float4* src = (const float4*)(enc_base + tile * ET_ * H_);
        float4* dst = (float4*)&sE[0][0];
#pragma unroll
        for (int i = 0; i < (ET_ * H_ / 4) / 256; ++i)
            dst[t + i * 256] = src[t + i * 256];
        __syncthreads();

        if (w < 4) {
            for (int el = 0; el < ET_; ++el) {
                float w0 = sS[w][tile * ET_ + el];
                float w1 = sS[w + 4][tile * ET_ + el];
                float4 ea = *(float4*)&sE[el][lane * 8];
                float4 eb = *(float4*)&sE[el][lane * 8 + 4];
                acc0[0] += w0 * ea.x;  acc1[0] += w1 * ea.x;
                acc0[1] += w0 * ea.y;  acc1[1] += w1 * ea.y;
                acc0[2] += w0 * ea.z;  acc1[2] += w1 * ea.z;
                acc0[3] += w0 * ea.w;  acc1[3] += w1 * ea.w;
                acc0[4] += w0 * eb.x;  acc1[4] += w1 * eb.x;
                acc0[5] += w0 * eb.y;  acc1[5] += w1 * eb.y;
                acc0[6] += w0 * eb.z;  acc1[6] += w1 * eb.z;
                acc0[7] += w0 * eb.w;  acc1[7] += w1 * eb.w;
            }
        }
        __syncthreads();
    }

    if (w < 4) {
        float* c0 = out + (b * TD_ + d0 + w) * H_ + lane * 8;
        float* c1 = out + (b * TD_ + d0 + w + 4) * H_ + lane * 8;
        float4 o;
        o.x = acc0[0]; o.y = acc0[1]; o.z = acc0[2]; o.w = acc0[3];
        *(float4*)(c0) = o;
        o.x = acc0[4]; o.y = acc0[5]; o.z = acc0[6]; o.w = acc0[7];
        *(float4*)(c0 + 4) = o;
        o.x = acc1[0]; o.y = acc1[1]; o.z = acc1[2]; o.w = acc1[3];
        *(float4*)(c1) = o;
        o.x = acc1[4]; o.y = acc1[5]; o.z = acc1[6]; o.w = acc1[7];
        *(float4*)(c1 + 4) = o;
    }
}

// ---------------------------------------------------------------------------
extern "C" void kernel_launch(void* const* d_in, const int* in_sizes, int n_in,
                              void* d_out, int out_size)
{
    const float* enc = (const float*)d_in[0];   // [B,TE,H]
    const float* dec = (const float*)d_in[1];   // [B,TD,H]
    const float* Wa  = (const float*)d_in[2];   // [H,H]
    const float* Ua  = (const float*)d_in[3];   // [H,H]
    const float* Va  = (const float*)d_in[4];   // [H,1]
    float* out = (float*)d_out;                 // context [B,TD,H] then weights [B,TD,TE]

    // Projections: enc@Wa (z=0, 32x4 blocks) and dec@Ua (z=1, 8x4 blocks)
    proj_kernel<<<dim3(32, 4, 2), 256>>>(enc, dec, Wa, Ua);

    // Fused score/softmax/context: 128 blocks
    attn_kernel<<<dim3(B_ * (TD_ / DT_)), 256>>>(enc, Va, out);
}

// round 4
// speedup vs baseline: 1.7467x; 1.7467x over previous
#include <cuda_runtime.h>

#define B_   8
#define TE_  512
#define TD_  128
#define H_   256

// Scratch (allocation-free rule: device globals)
__device__ float g_ep[B_ * TE_ * H_];      // enc @ W_a   [B,TE,H]
__device__ float g_dp[B_ * TD_ * H_];      // dec @ U_a   [B,TD,H]
__device__ float g_score[B_ * TD_ * TE_];  // raw scores  [B,TD,TE]

__device__ __forceinline__ float tanh_fast(float x) {
    float y;
    asm("tanh.approx.f32 %0, %1;" : "=f"(y) : "f"(x));
    return y;
}

// ---------------------------------------------------------------------------
// Fused projection GEMM. z=0: enc[4096,256] @ W_a ; z=1: dec[1024,256] @ U_a
// BM=128, BN=64, BK=16, 256 threads, 8x4 register tile per thread.
// ---------------------------------------------------------------------------
__global__ __launch_bounds__(256) void proj_kernel(
    const float* __restrict__ enc, const float* __restrict__ dec,
    const float* __restrict__ Wa,  const float* __restrict__ Ua)
{
    const int z = blockIdx.z;
    if (z == 1 && blockIdx.x >= (B_ * TD_) / 128) return;

    const float* __restrict__ A = z ? dec : enc;
    const float* __restrict__ W = z ? Ua  : Wa;
    float* __restrict__ P       = z ? g_dp : g_ep;

    __shared__ float As[16][132];   // A^T tile: As[k][m]
    __shared__ float Ws[16][68];    // Ws[k][n]

    const int bm = blockIdx.x * 128;
    const int bn = blockIdx.y * 64;
    const int t  = threadIdx.x;
    const int tx = t & 15;          // n quad
    const int ty = t >> 4;          // m octet

    float acc[8][4];
#pragma unroll
    for (int i = 0; i < 8; i++)
#pragma unroll
        for (int j = 0; j < 4; j++) acc[i][j] = 0.f;

    const int rowA = t >> 2;
    const int kqA  = t & 3;
    const int kkW  = t >> 4;
    const int nqW  = t & 15;

    for (int k0 = 0; k0 < H_; k0 += 16) {
        {
            float4 a0 = *(const float4*)&A[(bm + rowA) * H_ + k0 + kqA * 4];
            As[kqA * 4 + 0][rowA] = a0.x;
            As[kqA * 4 + 1][rowA] = a0.y;
            As[kqA * 4 + 2][rowA] = a0.z;
            As[kqA * 4 + 3][rowA] = a0.w;
            float4 a1 = *(const float4*)&A[(bm + rowA + 64) * H_ + k0 + kqA * 4];
            As[kqA * 4 + 0][rowA + 64] = a1.x;
            As[kqA * 4 + 1][rowA + 64] = a1.y;
            As[kqA * 4 + 2][rowA + 64] = a1.z;
            As[kqA * 4 + 3][rowA + 64] = a1.w;
            *(float4*)&Ws[kkW][nqW * 4] =
                *(const float4*)&W[(k0 + kkW) * H_ + bn + nqW * 4];
        }
        __syncthreads();

#pragma unroll
        for (int k = 0; k < 16; k++) {
            float4 a0 = *(float4*)&As[k][ty * 8];
            float4 a1 = *(float4*)&As[k][ty * 8 + 4];
            float4 b  = *(float4*)&Ws[k][tx * 4];
            float av[8] = {a0.x, a0.y, a0.z, a0.w, a1.x, a1.y, a1.z, a1.w};
            float bv[4] = {b.x, b.y, b.z, b.w};
#pragma unroll
            for (int i = 0; i < 8; i++)
#pragma unroll
                for (int j = 0; j < 4; j++) acc[i][j] += av[i] * bv[j];
        }
        __syncthreads();
    }

#pragma unroll
    for (int i = 0; i < 8; i++) {
        float4 o = {acc[i][0], acc[i][1], acc[i][2], acc[i][3]};
        *(float4*)&P[(bm + ty * 8 + i) * H_ + bn + tx * 4] = o;
    }
}

// ---------------------------------------------------------------------------
// Score kernel: g_score[b,d,e] = sum_h V[h]*tanh(ep[b,e,h] + dp[b,d,h])
// Grid: (TE/32, TD/8, B) = (16,16,8) = 2048 blocks, 256 threads.
// Warp w owns decoder row d0+w; lane owns encoder row e0+lane.
// ep staged transposed [h][e] (pad 33 -> conflict-free both ways);
// dp and V broadcast from SMEM as float4. No shuffles in the hot loop.
// ---------------------------------------------------------------------------
__global__ __launch_bounds__(256) void score_kernel(const float* __restrict__ V)
{
    __shared__ float sET[64][33];    // 8.4 KB, transposed ep tile
    __shared__ float sdp[8][256];    // 8 KB, dec_proj rows for this block
    __shared__ float sV[256];        // 1 KB

    const int t    = threadIdx.x;
    const int lane = t & 31;
    const int w    = t >> 5;
    const int b    = blockIdx.z;
    const int d0   = blockIdx.y * 8;
    const int e0   = blockIdx.x * 32;

    // Stage dp (8 rows x 256) and V once.
    {
        const float4* dpsrc = (const float4*)(g_dp + (b * TD_ + d0) * H_);
        ((float4*)sdp)[t]       = dpsrc[t];
        ((float4*)sdp)[t + 256] = dpsrc[t + 256];
        if (t < 64) ((float4*)sV)[t] = ((const float4*)V)[t];
    }

    const float* ep = g_ep + b * TE_ * H_;
    float acc0 = 0.f, acc1 = 0.f;

    const int e_stg = t >> 3;        // 0..31
    const int hq    = t & 7;         // 0..7

    for (int ht = 0; ht < 4; ++ht) {
        __syncthreads();             // covers dp staging on first iter
        // Stage sET[h][e] for h-tile: 32 e rows x 64 h
        {
            const float* eprow = ep + (e0 + e_stg) * H_ + ht * 64;
            float4 v0 = *(const float4*)(eprow + hq * 4);
            float4 v1 = *(const float4*)(eprow + 32 + hq * 4);
            sET[hq * 4 + 0][e_stg] = v0.x;
            sET[hq * 4 + 1][e_stg] = v0.y;
            sET[hq * 4 + 2][e_stg] = v0.z;
            sET[hq * 4 + 3][e_stg] = v0.w;
            sET[32 + hq * 4 + 0][e_stg] = v1.x;
            sET[32 + hq * 4 + 1][e_stg] = v1.y;
            sET[32 + hq * 4 + 2][e_stg] = v1.z;
            sET[32 + hq * 4 + 3][e_stg] = v1.w;
        }
        __syncthreads();

        const float* dprow = &sdp[w][ht * 64];
        const float* vrow  = &sV[ht * 64];
#pragma unroll
        for (int h = 0; h < 64; h += 4) {
            float4 dv = *(const float4*)(dprow + h);
            float4 vv = *(const float4*)(vrow + h);
            acc0 += vv.x * tanh_fast(sET[h + 0][lane] + dv.x);
            acc1 += vv.y * tanh_fast(sET[h + 1][lane] + dv.y);
            acc0 += vv.z * tanh_fast(sET[h + 2][lane] + dv.z);
            acc1 += vv.w * tanh_fast(sET[h + 3][lane] + dv.w);
        }
    }

    g_score[(b * TD_ + d0 + w) * TE_ + e0 + lane] = acc0 + acc1;
}

// ---------------------------------------------------------------------------
// Softmax + context. Grid: (2 h-halves, TD/16, B) = 128 blocks, 256 threads.
// Warp w softmaxes rows d0+w and d0+w+8, then accumulates context for both
// rows over its 4 h-channels (8 FFMA per sE LDS.128).
// ---------------------------------------------------------------------------
__global__ __launch_bounds__(256) void ctx_kernel(
    const float* __restrict__ enc, float* __restrict__ out)
{
    __shared__ float sE[64][128];    // 32 KB enc tile
    __shared__ float sW[16][512];    // 32 KB weights

    const int t    = threadIdx.x;
    const int lane = t & 31;
    const int w    = t >> 5;
    const int b    = blockIdx.z;
    const int d0   = blockIdx.y * 16;
    const int h0   = blockIdx.x * 128;

    // ---- softmax: warp w handles local rows w and w+8 ----
#pragma unroll
    for (int half = 0; half < 2; ++half) {
        const int dl = w + half * 8;
        const float4* srow =
            (const float4*)(g_score + (b * TD_ + d0 + dl) * TE_);
        float4 v[4];
        float m = -1e30f;
#pragma unroll
        for (int i = 0; i < 4; i++) {
            v[i] = srow[lane + 32 * i];
            m = fmaxf(m, fmaxf(fmaxf(v[i].x, v[i].y), fmaxf(v[i].z, v[i].w)));
        }
#pragma unroll
        for (int o = 16; o > 0; o >>= 1)
            m = fmaxf(m, __shfl_xor_sync(0xffffffffu, m, o));
        float sum = 0.f;
#pragma unroll
        for (int i = 0; i < 4; i++) {
            v[i].x = __expf(v[i].x - m);
            v[i].y = __expf(v[i].y - m);
            v[i].z = __expf(v[i].z - m);
            v[i].w = __expf(v[i].w - m);
            sum += v[i].x + v[i].y + v[i].z + v[i].w;
        }
#pragma unroll
        for (int o = 16; o > 0; o >>= 1)
            sum += __shfl_xor_sync(0xffffffffu, sum, o);
        const float inv = __fdividef(1.f, sum);
        float4* wrow = (float4*)&sW[dl][0];
        float4* gout = (float4*)(out + (size_t)B_ * TD_ * H_ +
                                 (b * TD_ + d0 + dl) * TE_);
#pragma unroll
        for (int i = 0; i < 4; i++) {
            v[i].x *= inv; v[i].y *= inv; v[i].z *= inv; v[i].w *= inv;
            wrow[lane + 32 * i] = v[i];
            if (blockIdx.x == 0) gout[lane + 32 * i] = v[i];
        }
    }
    __syncthreads();

    // ---- context ----
    float4 accA = {0.f, 0.f, 0.f, 0.f};
    float4 accB = {0.f, 0.f, 0.f, 0.f};
    const float* enc_b = enc + b * TE_ * H_;

    for (int et = 0; et < 8; ++et) {
        // stage sE: 64 e-rows x 128 h
        {
            const float* src = enc_b + et * 64 * H_ + h0;
#pragma unroll
            for (int i = 0; i < 8; i++) {
                int idx = t + i * 256;          // 0..2047 float4 slots
                int row = idx >> 5;
                int col = (idx & 31) * 4;
                *(float4*)&sE[row][col] = *(const float4*)(src + row * H_ + col);
            }
        }
        __syncthreads();

#pragma unroll 4
        for (int e = 0; e < 64; ++e) {
            float wa = sW[w][et * 64 + e];
            float wb = sW[w + 8][et * 64 + e];
            float4 ev = *(float4*)&sE[e][lane * 4];
            accA.x += wa * ev.x; accA.y += wa * ev.y;
            accA.z += wa * ev.z; accA.w += wa * ev.w;
            accB.x += wb * ev.x; accB.y += wb * ev.y;
            accB.z += wb * ev.z; accB.w += wb * ev.w;
        }
        __syncthreads();
    }

    *(float4*)(out + (b * TD_ + d0 + w) * H_ + h0 + lane * 4)     = accA;
    *(float4*)(out + (b * TD_ + d0 + w + 8) * H_ + h0 + lane * 4) = accB;
}

// ---------------------------------------------------------------------------
extern "C" void kernel_launch(void* const* d_in, const int* in_sizes, int n_in,
                              void* d_out, int out_size)
{
    const float* enc = (const float*)d_in[0];   // [B,TE,H]
    const float* dec = (const float*)d_in[1];   // [B,TD,H]
    const float* Wa  = (const float*)d_in[2];   // [H,H]
    const float* Ua  = (const float*)d_in[3];   // [H,H]
    const float* Va  = (const float*)d_in[4];   // [H,1]
    float* out = (float*)d_out;                 // context [B,TD,H] then weights [B,TD,TE]

    proj_kernel<<<dim3(32, 4, 2), 256>>>(enc, dec, Wa, Ua);
    score_kernel<<<dim3(TE_ / 32, TD_ / 8, B_), 256>>>(Va);
    ctx_kernel<<<dim3(2, TD_ / 16, B_), 256>>>(enc, out);
}

// round 5
// speedup vs baseline: 1.9416x; 1.1116x over previous
#include <cuda_runtime.h>

#define B_   8
#define TE_  512
#define TD_  128
#define H_   256

// Scratch (allocation-free rule: device globals)
__device__ float g_ep[B_ * TE_ * H_];      // enc @ W_a   [B,TE,H]
__device__ float g_dp[B_ * TD_ * H_];      // dec @ U_a   [B,TD,H]
__device__ float g_score[B_ * TD_ * TE_];  // raw scores -> weights (in place)

__device__ __forceinline__ float tanh_fast(float x) {
    float y;
    asm("tanh.approx.f32 %0, %1;" : "=f"(y) : "f"(x));
    return y;
}

// Packed fp32 pair FMA (Blackwell FFMA2): d = a*b + d, two lanes at once.
__device__ __forceinline__ void ffma2(unsigned long long& d,
                                      unsigned long long a,
                                      unsigned long long b) {
    asm("fma.rn.f32x2 %0, %1, %2, %0;" : "+l"(d) : "l"(a), "l"(b));
}
__device__ __forceinline__ unsigned long long rep2(float x) {
    unsigned long long p;
    asm("mov.b64 %0, {%1, %1};" : "=l"(p) : "r"(__float_as_uint(x)));
    return p;
}
__device__ __forceinline__ void unpk2(unsigned long long v,
                                      float& lo, float& hi) {
    unsigned a, b;
    asm("mov.b64 {%0, %1}, %2;" : "=r"(a), "=r"(b) : "l"(v));
    lo = __uint_as_float(a);
    hi = __uint_as_float(b);
}

// ---------------------------------------------------------------------------
// Projection GEMM, FFMA2 edition.
// BM=64, BN=32, BK=16, 128 threads, thread tile 8(m)x2(n) packed along m.
// Grid: 1D, blocks [0,512) = enc@Wa, [512,640) = dec@Ua. 640 blocks.
// ---------------------------------------------------------------------------
__global__ __launch_bounds__(128) void proj_kernel(
    const float* __restrict__ enc, const float* __restrict__ dec,
    const float* __restrict__ Wa,  const float* __restrict__ Ua)
{
    __shared__ float As[16][68];    // A^T tile: As[k][m]  (4.3 KB)
    __shared__ float Ws[16][36];    // Ws[k][n]            (2.3 KB)

    const int bid = blockIdx.x;
    const float* __restrict__ A;
    const float* __restrict__ W;
    float* __restrict__ P;
    int bm, bn;
    if (bid < 512) {
        A = enc; W = Wa; P = g_ep;
        bm = (bid >> 3) * 64; bn = (bid & 7) * 32;
    } else {
        const int r = bid - 512;
        A = dec; W = Ua; P = g_dp;
        bm = (r >> 3) * 64; bn = (r & 7) * 32;
    }

    const int t  = threadIdx.x;
    const int tx = t & 15;          // n pair: n = tx*2
    const int ty = t >> 4;          // m octet: m = ty*8

    unsigned long long acc[4][2];
#pragma unroll
    for (int i = 0; i < 4; i++) { acc[i][0] = 0ull; acc[i][1] = 0ull; }

    const int rowA = t >> 2;        // 0..31
    const int kqA  = t & 3;         // 0..3
    const int kkW  = t >> 3;        // 0..15
    const int nqW  = t & 7;         // 0..7

    // Prefetch tile 0
    float4 a0 = *(const float4*)&A[(bm + rowA) * H_ + kqA * 4];
    float4 a1 = *(const float4*)&A[(bm + rowA + 32) * H_ + kqA * 4];
    float4 wv = *(const float4*)&W[kkW * H_ + bn + nqW * 4];

    for (int k0 = 0; k0 < H_; k0 += 16) {
        // Store staged regs to SMEM
        As[kqA * 4 + 0][rowA] = a0.x;
        As[kqA * 4 + 1][rowA] = a0.y;
        As[kqA * 4 + 2][rowA] = a0.z;
        As[kqA * 4 + 3][rowA] = a0.w;
        As[kqA * 4 + 0][rowA + 32] = a1.x;
        As[kqA * 4 + 1][rowA + 32] = a1.y;
        As[kqA * 4 + 2][rowA + 32] = a1.z;
        As[kqA * 4 + 3][rowA + 32] = a1.w;
        *(float4*)&Ws[kkW][nqW * 4] = wv;
        __syncthreads();

        // Prefetch next tile while computing this one
        if (k0 + 16 < H_) {
            a0 = *(const float4*)&A[(bm + rowA) * H_ + k0 + 16 + kqA * 4];
            a1 = *(const float4*)&A[(bm + rowA + 32) * H_ + k0 + 16 + kqA * 4];
            wv = *(const float4*)&W[(k0 + 16 + kkW) * H_ + bn + nqW * 4];
        }

#pragma unroll
        for (int k = 0; k < 16; k++) {
            ulonglong2 aP = *(const ulonglong2*)&As[k][ty * 8];      // m pairs (0,1),(2,3)
            ulonglong2 aQ = *(const ulonglong2*)&As[k][ty * 8 + 4];  // (4,5),(6,7)
            float2 bv = *(const float2*)&Ws[k][tx * 2];
            unsigned long long b0 = rep2(bv.x);
            unsigned long long b1 = rep2(bv.y);
            ffma2(acc[0][0], aP.x, b0);  ffma2(acc[0][1], aP.x, b1);
            ffma2(acc[1][0], aP.y, b0);  ffma2(acc[1][1], aP.y, b1);
            ffma2(acc[2][0], aQ.x, b0);  ffma2(acc[2][1], aQ.x, b1);
            ffma2(acc[3][0], aQ.y, b0);  ffma2(acc[3][1], aQ.y, b1);
        }
        __syncthreads();
    }

#pragma unroll
    for (int i2 = 0; i2 < 4; i2++) {
        float l0, h0f, l1, h1f;
        unpk2(acc[i2][0], l0, h0f);       // col n+0: rows (m0, m0+1)
        unpk2(acc[i2][1], l1, h1f);       // col n+1
        float2 r0 = {l0, l1};
        float2 r1 = {h0f, h1f};
        *(float2*)&P[(bm + ty * 8 + i2 * 2    ) * H_ + bn + tx * 2] = r0;
        *(float2*)&P[(bm + ty * 8 + i2 * 2 + 1) * H_ + bn + tx * 2] = r1;
    }
}

// ---------------------------------------------------------------------------
// Score kernel (unchanged, MUFU-bound at floor).
// Grid: (TE/32, TD/8, B) = 2048 blocks, 256 threads.
// ---------------------------------------------------------------------------
__global__ __launch_bounds__(256) void score_kernel(const float* __restrict__ V)
{
    __shared__ float sET[64][33];
    __shared__ float sdp[8][256];
    __shared__ float sV[256];

    const int t    = threadIdx.x;
    const int lane = t & 31;
    const int w    = t >> 5;
    const int b    = blockIdx.z;
    const int d0   = blockIdx.y * 8;
    const int e0   = blockIdx.x * 32;

    {
        const float4* dpsrc = (const float4*)(g_dp + (b * TD_ + d0) * H_);
        ((float4*)sdp)[t]       = dpsrc[t];
        ((float4*)sdp)[t + 256] = dpsrc[t + 256];
        if (t < 64) ((float4*)sV)[t] = ((const float4*)V)[t];
    }

    const float* ep = g_ep + b * TE_ * H_;
    float acc0 = 0.f, acc1 = 0.f;

    const int e_stg = t >> 3;
    const int hq    = t & 7;

    for (int ht = 0; ht < 4; ++ht) {
        __syncthreads();
        {
            const float* eprow = ep + (e0 + e_stg) * H_ + ht * 64;
            float4 v0 = *(const float4*)(eprow + hq * 4);
            float4 v1 = *(const float4*)(eprow + 32 + hq * 4);
            sET[hq * 4 + 0][e_stg] = v0.x;
            sET[hq * 4 + 1][e_stg] = v0.y;
            sET[hq * 4 + 2][e_stg] = v0.z;
            sET[hq * 4 + 3][e_stg] = v0.w;
            sET[32 + hq * 4 + 0][e_stg] = v1.x;
            sET[32 + hq * 4 + 1][e_stg] = v1.y;
            sET[32 + hq * 4 + 2][e_stg] = v1.z;
            sET[32 + hq * 4 + 3][e_stg] = v1.w;
        }
        __syncthreads();

        const float* dprow = &sdp[w][ht * 64];
        const float* vrow  = &sV[ht * 64];
#pragma unroll
        for (int h = 0; h < 64; h += 4) {
            float4 dv = *(const float4*)(dprow + h);
            float4 vv = *(const float4*)(vrow + h);
            acc0 += vv.x * tanh_fast(sET[h + 0][lane] + dv.x);
            acc1 += vv.y * tanh_fast(sET[h + 1][lane] + dv.y);
            acc0 += vv.z * tanh_fast(sET[h + 2][lane] + dv.z);
            acc1 += vv.w * tanh_fast(sET[h + 3][lane] + dv.w);
        }
    }

    g_score[(b * TD_ + d0 + w) * TE_ + e0 + lane] = acc0 + acc1;
}

// ---------------------------------------------------------------------------
// Softmax: normalizes g_score in place and writes the weights output.
// Grid: 128 blocks x 8 warps = 1024 rows; 1 row per warp.
// ---------------------------------------------------------------------------
__global__ __launch_bounds__(256) void softmax_kernel(float* __restrict__ out)
{
    const int t    = threadIdx.x;
    const int lane = t & 31;
    const int w    = t >> 5;
    const int row  = blockIdx.x * 8 + w;     // = b*TD + d

    float4* srow = (float4*)(g_score + row * TE_);
    float4 v[4];
    float m = -1e30f;
#pragma unroll
    for (int i = 0; i < 4; i++) {
        v[i] = srow[lane + 32 * i];
        m = fmaxf(m, fmaxf(fmaxf(v[i].x, v[i].y), fmaxf(v[i].z, v[i].w)));
    }
#pragma unroll
    for (int o = 16; o > 0; o >>= 1)
        m = fmaxf(m, __shfl_xor_sync(0xffffffffu, m, o));
    float sum = 0.f;
#pragma unroll
    for (int i = 0; i < 4; i++) {
        v[i].x = __expf(v[i].x - m);
        v[i].y = __expf(v[i].y - m);
        v[i].z = __expf(v[i].z - m);
        v[i].w = __expf(v[i].w - m);
        sum += v[i].x + v[i].y + v[i].z + v[i].w;
    }
#pragma unroll
    for (int o = 16; o > 0; o >>= 1)
        sum += __shfl_xor_sync(0xffffffffu, sum, o);
    const float inv = __fdividef(1.f, sum);
    float4* gout = (float4*)(out + (size_t)B_ * TD_ * H_ + row * TE_);
#pragma unroll
    for (int i = 0; i < 4; i++) {
        v[i].x *= inv; v[i].y *= inv; v[i].z *= inv; v[i].w *= inv;
        srow[lane + 32 * i] = v[i];
        gout[lane + 32 * i] = v[i];
    }
}

// ---------------------------------------------------------------------------
// Context: 4 decoder rows per warp (1B LDS per MAC), FFMA2 accumulators.
// Grid: (H/64, TD/32, B) = (4,4,8) = 128 blocks, 256 threads.
// Warp w owns rows d0 + w + {0,8,16,24}; lane owns h pair h0 + 2*lane.
// ---------------------------------------------------------------------------
__global__ __launch_bounds__(256) void ctx_kernel(
    const float* __restrict__ enc, float* __restrict__ out)
{
    __shared__ float sE[128][64];    // 32 KB: enc e-tile
    __shared__ float sWt[32][128];   // 16 KB: weights chunk [d][e]

    const int t    = threadIdx.x;
    const int lane = t & 31;
    const int w    = t >> 5;
    const int b    = blockIdx.z;
    const int d0   = blockIdx.y * 32;
    const int h0   = blockIdx.x * 64;

    unsigned long long acc[4] = {0ull, 0ull, 0ull, 0ull};
    const float* enc_b = enc + b * TE_ * H_;
    const float* wbase = g_score + (b * TD_ + d0) * TE_;

    for (int et = 0; et < 4; ++et) {
        // stage sE: 128 e-rows x 64 h
#pragma unroll
        for (int i = 0; i < 8; i++) {
            int idx = t + i * 256;           // 2048 float4 slots
            int row = idx >> 4, col = (idx & 15) * 4;
            *(float4*)&sE[row][col] =
                *(const float4*)&enc_b[(et * 128 + row) * H_ + h0 + col];
        }
        // stage sWt: 32 d-rows x 128 e
#pragma unroll
        for (int i = 0; i < 4; i++) {
            int idx = t + i * 256;           // 1024 float4 slots
            int row = idx >> 5, col = (idx & 31) * 4;
            *(float4*)&sWt[row][col] =
                *(const float4*)&wbase[row * TE_ + et * 128 + col];
        }
        __syncthreads();

#pragma unroll 2
        for (int e4 = 0; e4 < 32; ++e4) {
            float4 wr0 = *(const float4*)&sWt[w     ][e4 * 4];
            float4 wr1 = *(const float4*)&sWt[w +  8][e4 * 4];
            float4 wr2 = *(const float4*)&sWt[w + 16][e4 * 4];
            float4 wr3 = *(const float4*)&sWt[w + 24][e4 * 4];
            const float* f0 = (const float*)&wr0;
            const float* f1 = (const float*)&wr1;
            const float* f2 = (const float*)&wr2;
            const float* f3 = (const float*)&wr3;
#pragma unroll
            for (int j = 0; j < 4; j++) {
                unsigned long long ev =
                    *(const unsigned long long*)&sE[e4 * 4 + j][lane * 2];
                ffma2(acc[0], rep2(f0[j]), ev);
                ffma2(acc[1], rep2(f1[j]), ev);
                ffma2(acc[2], rep2(f2[j]), ev);
                ffma2(acc[3], rep2(f3[j]), ev);
            }
        }
        __syncthreads();
    }

#pragma unroll
    for (int r = 0; r < 4; r++) {
        float lo, hi;
        unpk2(acc[r], lo, hi);
        float2 o = {lo, hi};
        *(float2*)&out[(b * TD_ + d0 + w + 8 * r) * H_ + h0 + lane * 2] = o;
    }
}

// ---------------------------------------------------------------------------
extern "C" void kernel_launch(void* const* d_in, const int* in_sizes, int n_in,
                              void* d_out, int out_size)
{
    const float* enc = (const float*)d_in[0];   // [B,TE,H]
    const float* dec = (const float*)d_in[1];   // [B,TD,H]
    const float* Wa  = (const float*)d_in[2];   // [H,H]
    const float* Ua  = (const float*)d_in[3];   // [H,H]
    const float* Va  = (const float*)d_in[4];   // [H,1]
    float* out = (float*)d_out;                 // context [B,TD,H] then weights [B,TD,TE]

    proj_kernel<<<dim3(640), 128>>>(enc, dec, Wa, Ua);
    score_kernel<<<dim3(TE_ / 32, TD_ / 8, B_), 256>>>(Va);
    softmax_kernel<<<dim3(128), 256>>>(out);
    ctx_kernel<<<dim3(H_ / 64, TD_ / 32, B_), 256>>>(enc, out);
}